// round 15
// baseline (speedup 1.0000x reference)
#include <cuda_runtime.h>
#include <cstdint>

// Problem constants
#define BB 4
#define SS 512     // SX == SY
#define HH 128     // H
#define DD 256     // 2H

// Scratch for projections (no cudaMalloc allowed)
__device__ float g_s1[BB * SS * HH];   // s1[b,s,h]
__device__ float g_s2[BB * SS * HH];   // s2[b,t,h]

__device__ __forceinline__ float tanh_fast(float v) {
    float r;
    asm("tanh.approx.f32 %0, %1;" : "=f"(r) : "f"(v));
    return r;
}

// ---------------------------------------------------------------------------
// Kernel A: projections. s1 = x @ W1^T, s2 = y @ W2^T  (unchanged, ~7us)
// ---------------------------------------------------------------------------
#define GA_THREADS 256
#define WPITCH 132

__global__ __launch_bounds__(GA_THREADS)
void proj_kernel(const float* __restrict__ x, const float* __restrict__ y,
                 const float* __restrict__ W1, const float* __restrict__ W2)
{
    extern __shared__ float sm[];
    float* Wsm   = sm;                    // [256][WPITCH]  (Wsm[k][h] = W[h][k])
    float* rowsm = sm + 256 * WPITCH;     // [32][256]

    const int part = blockIdx.x >> 6;
    const int cta  = blockIdx.x & 63;
    const float* W   = part ? W2 : W1;
    const float* src = part ? y  : x;
    float* dst = part ? g_s2 : g_s1;

    const int tid = threadIdx.x;

    {
        const float4* W4 = (const float4*)W;
        const int h   = tid & 127;
        const int kq0 = tid >> 7;
        #pragma unroll
        for (int i = 0; i < 32; i++) {
            const int kq = kq0 + 2 * i;
            float4 wv = W4[h * 64 + kq];
            Wsm[(4 * kq + 0) * WPITCH + h] = wv.x;
            Wsm[(4 * kq + 1) * WPITCH + h] = wv.y;
            Wsm[(4 * kq + 2) * WPITCH + h] = wv.z;
            Wsm[(4 * kq + 3) * WPITCH + h] = wv.w;
        }
    }

    const int r0 = cta * 32;
    {
        const float4* s4 = (const float4*)(src + (size_t)r0 * DD);
        float4* d4 = (float4*)rowsm;
        #pragma unroll
        for (int i = 0; i < 8; i++)
            d4[tid + GA_THREADS * i] = s4[tid + GA_THREADS * i];
    }
    __syncthreads();

    const int w = tid >> 5, lane = tid & 31;
    float4 a0 = {0,0,0,0}, a1 = {0,0,0,0}, a2 = {0,0,0,0}, a3 = {0,0,0,0};
    const float* rb = rowsm + (w * 4) * DD;

    #pragma unroll 4
    for (int k = 0; k < DD; k++) {
        float4 wv = *(const float4*)&Wsm[k * WPITCH + lane * 4];
        float x0 = rb[k];
        float x1 = rb[DD + k];
        float x2 = rb[2 * DD + k];
        float x3 = rb[3 * DD + k];
        a0.x += x0 * wv.x; a0.y += x0 * wv.y; a0.z += x0 * wv.z; a0.w += x0 * wv.w;
        a1.x += x1 * wv.x; a1.y += x1 * wv.y; a1.z += x1 * wv.z; a1.w += x1 * wv.w;
        a2.x += x2 * wv.x; a2.y += x2 * wv.y; a2.z += x2 * wv.z; a2.w += x2 * wv.w;
        a3.x += x3 * wv.x; a3.y += x3 * wv.y; a3.z += x3 * wv.z; a3.w += x3 * wv.w;
    }

    ((float4*)(dst + (size_t)(r0 + w * 4 + 0) * HH))[lane] = a0;
    ((float4*)(dst + (size_t)(r0 + w * 4 + 1) * HH))[lane] = a1;
    ((float4*)(dst + (size_t)(r0 + w * 4 + 2) * HH))[lane] = a2;
    ((float4*)(dst + (size_t)(r0 + w * 4 + 3) * HH))[lane] = a3;
}

// ---------------------------------------------------------------------------
// Kernel B: fused score + softmax + weighted sum.
// TY=4 t-rows per CTA, 2 warps per t (split s 2-way), grid=(128,4)=512 CTAs.
// 44.6KB smem -> 4 CTAs/SM -> ~28 warps/SM. 4 independent accumulators in the
// tanh loop (no serial FFMA chain).
// ---------------------------------------------------------------------------
#define TY 4
#define AT_THREADS 256
#define S2P 132                                   // padded pitch (s1/s2 rows)

#define V_OFF   (TY * S2P)                        // 528
#define SC_OFF  (V_OFF + 128)                     // 656
#define BUF_OFF (SC_OFF + TY * 512)               // 2704
#define BUF_FLOATS (64 * S2P)                     // 8448 (pass1: 64 rows; pass2: 32x256=8192)
#define SM_FLOATS (BUF_OFF + BUF_FLOATS)          // 11152 floats = 44608 B

__global__ __launch_bounds__(AT_THREADS, 4)
void attn_kernel(const float* __restrict__ x, const float* __restrict__ vc,
                 float* __restrict__ out)
{
    extern __shared__ float sm[];
    float* s2sm = sm;               // [TY][S2P] (cols 128..131 = pad, reused for softmax pair exch)
    float* vsm  = sm + V_OFF;       // [128]
    float* scsm = sm + SC_OFF;      // [TY][512] softmax weights
    float* buf  = sm + BUF_OFF;     // pass1: s1 tile [64][S2P]; pass2: x tile [32][256]

    const int b   = blockIdx.y;
    const int t0  = blockIdx.x * TY;
    const int tid = threadIdx.x, w = tid >> 5, lane = tid & 31;
    const int t_l = w >> 1;         // t within tile (0..3)
    const int sh  = w & 1;          // s-half owned by this warp

    // Load s2 rows for this t-tile and v (visible after first __syncthreads).
    {
        const int r = tid >> 6;                  // 0..3 (TY rows), 64 threads per row
        const int c4 = tid & 63;
        if (c4 < 32)
            *(float4*)&s2sm[r * S2P + c4 * 4] =
                *(const float4*)&g_s2[(size_t)(b * SS + t0 + r) * HH + c4 * 4];
        if (tid < 32)
            *(float4*)&vsm[tid * 4] = *(const float4*)&vc[tid * 4];
    }

    // ---- Pass 1: scores. Warp (t_l, sh) owns s = {64g + 32*sh + lane}, g=0..7
    float sc[8];
    const float* s2r = s2sm + t_l * S2P;

    for (int g = 0; g < 8; g++) {
        __syncthreads();
        // Stage 64 s1 rows [64][128] padded to S2P: 2048 float4, 8 per thread.
        #pragma unroll
        for (int i = 0; i < 8; i++) {
            const int f = tid + AT_THREADS * i;   // 0..2047
            const int r = f >> 5, c4 = f & 31;
            *(float4*)&buf[r * S2P + c4 * 4] =
                *(const float4*)&g_s1[(size_t)(b * SS + g * 64 + r) * HH + c4 * 4];
        }
        __syncthreads();

        const float* a = buf + (sh * 32 + lane) * S2P;   // conflict-free (pitch 132)
        float4 acc = {0.f, 0.f, 0.f, 0.f};
        #pragma unroll 8
        for (int h4 = 0; h4 < 32; h4++) {
            float4 av = *(const float4*)&a[h4 * 4];
            float4 bv = *(const float4*)&s2r[h4 * 4];    // broadcast
            float4 vv = *(const float4*)&vsm[h4 * 4];    // broadcast
            acc.x += tanh_fast(av.x + bv.x) * vv.x;
            acc.y += tanh_fast(av.y + bv.y) * vv.y;
            acc.z += tanh_fast(av.z + bv.z) * vv.z;
            acc.w += tanh_fast(av.w + bv.w) * vv.w;
        }
        sc[g] = (acc.x + acc.y) + (acc.z + acc.w);
    }

    // ---- Softmax: warp-local reduce, then combine across the warp pair ------
    float m = sc[0];
    #pragma unroll
    for (int i = 1; i < 8; i++) m = fmaxf(m, sc[i]);
    #pragma unroll
    for (int o = 16; o > 0; o >>= 1) m = fmaxf(m, __shfl_xor_sync(0xffffffffu, m, o));

    float p = 0.0f;
    #pragma unroll
    for (int i = 0; i < 8; i++) p += __expf(sc[i] - m);
    #pragma unroll
    for (int o = 16; o > 0; o >>= 1) p += __shfl_xor_sync(0xffffffffu, p, o);

    // exchange (m, p) with partner warp via s2sm pad columns
    float* pairx = s2sm + t_l * S2P + 128;
    if (lane == 0) { pairx[sh * 2] = m; pairx[sh * 2 + 1] = p; }
    __syncthreads();
    const float om = pairx[(sh ^ 1) * 2], op = pairx[(sh ^ 1) * 2 + 1];
    const float M  = fmaxf(m, om);
    const float S  = p * __expf(m - M) + op * __expf(om - M);
    const float inv = 1.0f / S;
    #pragma unroll
    for (int g = 0; g < 8; g++)
        scsm[t_l * 512 + g * 64 + sh * 32 + lane] = __expf(sc[g] - M) * inv;

    // ---- Pass 2: out[t,:] = sum_s w[s] * x[b,s,:] ---------------------------
    float4 acc0 = {0,0,0,0}, acc1 = {0,0,0,0};
    for (int sb = 0; sb < 16; sb++) {
        __syncthreads();
        const float4* xs = (const float4*)(x + (size_t)(b * SS + sb * 32) * DD);
        float4* bd = (float4*)buf;
        #pragma unroll
        for (int i = 0; i < 8; i++)
            bd[tid + AT_THREADS * i] = xs[tid + AT_THREADS * i];
        __syncthreads();

        if ((sb & 1) == sh) {
            const float* wr = scsm + t_l * 512 + sb * 32;
            #pragma unroll 8
            for (int j = 0; j < 32; j++) {
                const float wt = wr[j];                                  // broadcast
                float4 xa = *(const float4*)&buf[j * DD + lane * 4];
                float4 xb = *(const float4*)&buf[j * DD + 128 + lane * 4];
                acc0.x += wt * xa.x; acc0.y += wt * xa.y;
                acc0.z += wt * xa.z; acc0.w += wt * xa.w;
                acc1.x += wt * xb.x; acc1.y += wt * xb.y;
                acc1.z += wt * xb.z; acc1.w += wt * xb.w;
            }
        }
    }

    // ---- Pair-reduce the two partial outputs per t, then store --------------
    __syncthreads();                  // all warps done with buf as x-tile
    float* red = buf;                 // [TY][256]
    if (sh == 1) {
        *(float4*)&red[t_l * DD + lane * 4]       = acc0;
        *(float4*)&red[t_l * DD + 128 + lane * 4] = acc1;
    }
    __syncthreads();
    if (sh == 0) {
        float4 r0 = *(const float4*)&red[t_l * DD + lane * 4];
        float4 r1 = *(const float4*)&red[t_l * DD + 128 + lane * 4];
        acc0.x += r0.x; acc0.y += r0.y; acc0.z += r0.z; acc0.w += r0.w;
        acc1.x += r1.x; acc1.y += r1.y; acc1.z += r1.z; acc1.w += r1.w;
        float* o = out + (size_t)(b * SS + t0 + t_l) * DD;
        *(float4*)&o[lane * 4]       = acc0;
        *(float4*)&o[128 + lane * 4] = acc1;
    }
}

// ---------------------------------------------------------------------------
extern "C" void kernel_launch(void* const* d_in, const int* in_sizes, int n_in,
                              void* d_out, int out_size)
{
    const float* x   = (const float*)d_in[0];   // (4,512,256)
    const float* y   = (const float*)d_in[1];   // (4,512,256)
    const float* W1  = (const float*)d_in[2];   // (128,256)
    const float* W2  = (const float*)d_in[3];   // (128,256)
    const float* vc  = (const float*)d_in[4];   // (1,128)
    float* out = (float*)d_out;                 // (4,512,256)

    const size_t smA = (size_t)(256 * WPITCH + 32 * 256) * sizeof(float);
    const size_t smB = (size_t)SM_FLOATS * sizeof(float);   // 44608 B

    cudaFuncSetAttribute(proj_kernel, cudaFuncAttributeMaxDynamicSharedMemorySize, (int)smA);
    cudaFuncSetAttribute(attn_kernel, cudaFuncAttributeMaxDynamicSharedMemorySize, (int)smB);

    proj_kernel<<<128, GA_THREADS, smA>>>(x, y, W1, W2);
    attn_kernel<<<dim3(SS / TY, BB), AT_THREADS, smB>>>(x, vc, out);
}

// round 16
// speedup vs baseline: 1.2427x; 1.2427x over previous
#include <cuda_runtime.h>
#include <cstdint>

// Problem constants
#define BB 4
#define SS 512     // SX == SY
#define HH 128     // H
#define DD 256     // 2H

// Scratch (no cudaMalloc allowed)
// g_s1 is stored TRANSPOSED: s1T[b][h][s]  (s-major, contiguous in s)
__device__ float g_s1[BB * HH * SS];
// g_s2 stays row-major: s2[b][t][h]
__device__ float g_s2[BB * SS * HH];

__device__ __forceinline__ float tanh_fast(float v) {
    float r;
    asm("tanh.approx.f32 %0, %1;" : "=f"(r) : "f"(v));
    return r;
}

// ---------------------------------------------------------------------------
// Kernel A: projections. part0: s1T[b][h][s] = (x @ W1^T) transposed
//                        part1: s2[b][t][h]  =  y @ W2^T
// grid = 128 CTAs (64 per part), 256 threads, 32 rows per CTA.
// ---------------------------------------------------------------------------
#define GA_THREADS 256
#define WPITCH 132

__global__ __launch_bounds__(GA_THREADS)
void proj_kernel(const float* __restrict__ x, const float* __restrict__ y,
                 const float* __restrict__ W1, const float* __restrict__ W2)
{
    extern __shared__ float sm[];
    float* Wsm   = sm;                    // [256][WPITCH]  (Wsm[k][h] = W[h][k])
    float* rowsm = sm + 256 * WPITCH;     // [32][256]

    const int part = blockIdx.x >> 6;     // 0: x->s1T, 1: y->s2
    const int cta  = blockIdx.x & 63;
    const float* W   = part ? W2 : W1;
    const float* src = part ? y  : x;

    const int tid = threadIdx.x;

    // Load + transpose W into Wsm[k][h].
    {
        const float4* W4 = (const float4*)W;
        const int h   = tid & 127;
        const int kq0 = tid >> 7;
        #pragma unroll
        for (int i = 0; i < 32; i++) {
            const int kq = kq0 + 2 * i;
            float4 wv = W4[h * 64 + kq];
            Wsm[(4 * kq + 0) * WPITCH + h] = wv.x;
            Wsm[(4 * kq + 1) * WPITCH + h] = wv.y;
            Wsm[(4 * kq + 2) * WPITCH + h] = wv.z;
            Wsm[(4 * kq + 3) * WPITCH + h] = wv.w;
        }
    }

    const int r0 = cta * 32;              // global row (b*512 + s/t)
    {
        const float4* s4 = (const float4*)(src + (size_t)r0 * DD);
        float4* d4 = (float4*)rowsm;
        #pragma unroll
        for (int i = 0; i < 8; i++)
            d4[tid + GA_THREADS * i] = s4[tid + GA_THREADS * i];
    }
    __syncthreads();

    const int w = tid >> 5, lane = tid & 31;
    float acc[4][4];                      // [row i][h component q]
    #pragma unroll
    for (int i = 0; i < 4; i++)
        #pragma unroll
        for (int q = 0; q < 4; q++) acc[i][q] = 0.0f;

    const float* rb = rowsm + (w * 4) * DD;

    #pragma unroll 4
    for (int k = 0; k < DD; k++) {
        float4 wv = *(const float4*)&Wsm[k * WPITCH + lane * 4];
        float xr0 = rb[k];
        float xr1 = rb[DD + k];
        float xr2 = rb[2 * DD + k];
        float xr3 = rb[3 * DD + k];
        acc[0][0] += xr0 * wv.x; acc[0][1] += xr0 * wv.y; acc[0][2] += xr0 * wv.z; acc[0][3] += xr0 * wv.w;
        acc[1][0] += xr1 * wv.x; acc[1][1] += xr1 * wv.y; acc[1][2] += xr1 * wv.z; acc[1][3] += xr1 * wv.w;
        acc[2][0] += xr2 * wv.x; acc[2][1] += xr2 * wv.y; acc[2][2] += xr2 * wv.z; acc[2][3] += xr2 * wv.w;
        acc[3][0] += xr3 * wv.x; acc[3][1] += xr3 * wv.y; acc[3][2] += xr3 * wv.z; acc[3][3] += xr3 * wv.w;
    }

    if (part == 0) {
        // transposed store: s1T[b][h][s], h = lane*4+q, s = (r0&511) + w*4 + i
        const int b  = r0 >> 9;
        const int sl = (r0 & 511) + w * 4;
        #pragma unroll
        for (int q = 0; q < 4; q++) {
            float4 tv = make_float4(acc[0][q], acc[1][q], acc[2][q], acc[3][q]);
            *(float4*)&g_s1[(size_t)b * (HH * SS) + (size_t)(lane * 4 + q) * SS + sl] = tv;
        }
    } else {
        #pragma unroll
        for (int i = 0; i < 4; i++) {
            float4 ov = make_float4(acc[i][0], acc[i][1], acc[i][2], acc[i][3]);
            *(float4*)&g_s2[(size_t)(r0 + w * 4 + i) * HH + lane * 4] = ov;
        }
    }
}

// ---------------------------------------------------------------------------
// Kernel B: fused score + softmax + weighted sum.
// TY=8 t-rows per CTA, grid = (64, 4) = 256 CTAs, 256 threads (8 warps).
// Pass 1: warp (hh = w>>2, sidx = w&3) computes partial scores for all 8 t,
//         s in [sidx*128, +128), h in [hh*64, +64). s1T read via contiguous
//         LDG.128 from L2; s2 packed [h][8t] broadcast from smem. 32 indep
//         accumulators per lane. No smem staging, no barriers in the loop.
// Pass 2: warp w = t index; x tiles staged in smem, all warps active.
// ---------------------------------------------------------------------------
#define TY 8
#define AT_THREADS 256

// smem layout (floats)
#define S2PK_OFF 0                         // [128][8]  = 1024
#define V_OFF    1024                      // [128]
#define RED_OFF  1152                      // [64]: [0..31] max grid, [32..63] sum grid
#define PSUM_OFF 1216                      // [8][512] = 4096 (partials -> weights)
#define BUF_OFF  5312                      // [32][256] = 8192 (pass-2 x tile)
#define SM_FLOATS 13504                    // 54016 bytes

__global__ __launch_bounds__(AT_THREADS, 2)
void attn_kernel(const float* __restrict__ x, const float* __restrict__ vc,
                 float* __restrict__ out)
{
    extern __shared__ float sm[];
    float* s2pk = sm + S2PK_OFF;
    float* vsm  = sm + V_OFF;
    float* red  = sm + RED_OFF;
    float* psum = sm + PSUM_OFF;
    float* buf  = sm + BUF_OFF;

    const int b   = blockIdx.y;
    const int t0  = blockIdx.x * TY;
    const int tid = threadIdx.x, w = tid >> 5, lane = tid & 31;
    const int sidx = w & 3;               // s quarter
    const int hh   = w >> 2;              // h half

    // Build s2pk[h][t] (t fast) and vsm.
    if (tid < 128) {
        const int h = tid;
        #pragma unroll
        for (int t = 0; t < TY; t++)
            s2pk[h * TY + t] = g_s2[(size_t)(b * SS + t0 + t) * HH + h];
    } else if (tid < 160) {
        const int l = tid - 128;
        *(float4*)&vsm[l * 4] = *(const float4*)&vc[l * 4];
    }
    __syncthreads();

    // ---- Pass 1: partial scores ---------------------------------------------
    const int sbase = sidx * 128 + lane * 4;     // lane's 4 s values
    const float* s1p = g_s1 + (size_t)b * (HH * SS) + (size_t)(hh * 64) * SS + sbase;
    const float* s2h = s2pk + (hh * 64) * TY;
    const float* vh  = vsm + hh * 64;

    float acc[32];                                // [t][c]
    #pragma unroll
    for (int i = 0; i < 32; i++) acc[i] = 0.0f;

    #pragma unroll 2
    for (int h = 0; h < 64; h++) {
        float4 av  = *(const float4*)(s1p + (size_t)h * SS);   // contiguous LDG.128
        float4 bt0 = *(const float4*)(s2h + h * TY);           // broadcast: t 0..3
        float4 bt1 = *(const float4*)(s2h + h * TY + 4);       // broadcast: t 4..7
        float  vv  = vh[h];                                    // broadcast
        float ax[4] = {av.x, av.y, av.z, av.w};
        float bx[8] = {bt0.x, bt0.y, bt0.z, bt0.w, bt1.x, bt1.y, bt1.z, bt1.w};
        #pragma unroll
        for (int t = 0; t < 8; t++)
            #pragma unroll
            for (int c = 0; c < 4; c++)
                acc[t * 4 + c] += tanh_fast(ax[c] + bx[t]) * vv;
    }

    // ---- Combine h-halves + softmax ------------------------------------------
    if (hh == 1) {
        #pragma unroll
        for (int t = 0; t < 8; t++)
            *(float4*)&psum[t * 512 + sbase] =
                make_float4(acc[t*4], acc[t*4+1], acc[t*4+2], acc[t*4+3]);
    }
    __syncthreads();

    float gm[8];
    if (hh == 0) {
        #pragma unroll
        for (int t = 0; t < 8; t++) {
            float4 p = *(const float4*)&psum[t * 512 + sbase];
            acc[t*4+0] += p.x; acc[t*4+1] += p.y; acc[t*4+2] += p.z; acc[t*4+3] += p.w;
            float m = fmaxf(fmaxf(acc[t*4], acc[t*4+1]), fmaxf(acc[t*4+2], acc[t*4+3]));
            #pragma unroll
            for (int o = 16; o > 0; o >>= 1) m = fmaxf(m, __shfl_xor_sync(0xffffffffu, m, o));
            gm[t] = m;
        }
        if (lane == 0) {
            #pragma unroll
            for (int t = 0; t < 8; t++) red[sidx * 8 + t] = gm[t];
        }
    }
    __syncthreads();

    if (hh == 0) {
        #pragma unroll
        for (int t = 0; t < 8; t++) {
            float M = fmaxf(fmaxf(red[t], red[8 + t]), fmaxf(red[16 + t], red[24 + t]));
            gm[t] = M;
            float s = 0.0f;
            #pragma unroll
            for (int c = 0; c < 4; c++) {
                float e = __expf(acc[t*4+c] - M);
                acc[t*4+c] = e; s += e;
            }
            #pragma unroll
            for (int o = 16; o > 0; o >>= 1) s += __shfl_xor_sync(0xffffffffu, s, o);
            if (lane == 0) red[32 + sidx * 8 + t] = s;
        }
    }
    __syncthreads();

    if (hh == 0) {
        #pragma unroll
        for (int t = 0; t < 8; t++) {
            float S = (red[32 + t] + red[40 + t]) + (red[48 + t] + red[56 + t]);
            float inv = 1.0f / S;
            *(float4*)&psum[t * 512 + sbase] =
                make_float4(acc[t*4] * inv, acc[t*4+1] * inv, acc[t*4+2] * inv, acc[t*4+3] * inv);
        }
    }
    // ordering of psum writes handled by the first barrier of the pass-2 loop

    // ---- Pass 2: out[t,:] = sum_s w[t][s] * x[b,s,:] -------------------------
    // warp w = t index; lane covers d = lane*4 (low half) and 128+lane*4.
    float4 acc0 = {0,0,0,0}, acc1 = {0,0,0,0};
    for (int sb = 0; sb < 16; sb++) {
        __syncthreads();
        const float4* xs = (const float4*)(x + (size_t)(b * SS + sb * 32) * DD);
        float4* bd = (float4*)buf;
        #pragma unroll
        for (int i = 0; i < 8; i++)
            bd[tid + AT_THREADS * i] = xs[tid + AT_THREADS * i];
        __syncthreads();

        const float* wr = psum + w * 512 + sb * 32;
        #pragma unroll
        for (int jq = 0; jq < 8; jq++) {
            float4 w4 = *(const float4*)&wr[jq * 4];     // broadcast
            float wtv[4] = {w4.x, w4.y, w4.z, w4.w};
            #pragma unroll
            for (int c = 0; c < 4; c++) {
                const int j = jq * 4 + c;
                const float wt = wtv[c];
                float4 xa = *(const float4*)&buf[j * DD + lane * 4];
                float4 xb = *(const float4*)&buf[j * DD + 128 + lane * 4];
                acc0.x += wt * xa.x; acc0.y += wt * xa.y;
                acc0.z += wt * xa.z; acc0.w += wt * xa.w;
                acc1.x += wt * xb.x; acc1.y += wt * xb.y;
                acc1.z += wt * xb.z; acc1.w += wt * xb.w;
            }
        }
    }

    float* o = out + (size_t)(b * SS + t0 + w) * DD;
    *(float4*)&o[lane * 4]       = acc0;
    *(float4*)&o[128 + lane * 4] = acc1;
}

// ---------------------------------------------------------------------------
extern "C" void kernel_launch(void* const* d_in, const int* in_sizes, int n_in,
                              void* d_out, int out_size)
{
    const float* x   = (const float*)d_in[0];   // (4,512,256)
    const float* y   = (const float*)d_in[1];   // (4,512,256)
    const float* W1  = (const float*)d_in[2];   // (128,256)
    const float* W2  = (const float*)d_in[3];   // (128,256)
    const float* vc  = (const float*)d_in[4];   // (1,128)
    float* out = (float*)d_out;                 // (4,512,256)

    const size_t smA = (size_t)(256 * WPITCH + 32 * 256) * sizeof(float);
    const size_t smB = (size_t)SM_FLOATS * sizeof(float);   // 54016 B

    cudaFuncSetAttribute(proj_kernel, cudaFuncAttributeMaxDynamicSharedMemorySize, (int)smA);
    cudaFuncSetAttribute(attn_kernel, cudaFuncAttributeMaxDynamicSharedMemorySize, (int)smB);

    proj_kernel<<<128, GA_THREADS, smA>>>(x, y, W1, W2);
    attn_kernel<<<dim3(SS / TY, BB), AT_THREADS, smB>>>(x, vc, out);
}

// round 17
// speedup vs baseline: 1.2474x; 1.0037x over previous
#include <cuda_runtime.h>
#include <cstdint>

// Problem constants
#define BB 4
#define SS 512     // SX == SY
#define HH 128     // H
#define DD 256     // 2H

// Scratch (no cudaMalloc allowed)
// g_s1 is stored TRANSPOSED: s1T[b][h][s]  (s-major, contiguous in s)
__device__ float g_s1[BB * HH * SS];
// g_s2 stays row-major: s2[b][t][h]
__device__ float g_s2[BB * SS * HH];

__device__ __forceinline__ float tanh_fast(float v) {
    float r;
    asm("tanh.approx.f32 %0, %1;" : "=f"(r) : "f"(v));
    return r;
}

// ---------------------------------------------------------------------------
// Kernel A: projections. part0: s1T[b][h][s] = (x @ W1^T) transposed
//                        part1: s2[b][t][h]  =  y @ W2^T
// grid = 128 CTAs (64 per part), 256 threads, 32 rows per CTA.
// ---------------------------------------------------------------------------
#define GA_THREADS 256
#define WPITCH 132

__global__ __launch_bounds__(GA_THREADS)
void proj_kernel(const float* __restrict__ x, const float* __restrict__ y,
                 const float* __restrict__ W1, const float* __restrict__ W2)
{
    extern __shared__ float sm[];
    float* Wsm   = sm;                    // [256][WPITCH]  (Wsm[k][h] = W[h][k])
    float* rowsm = sm + 256 * WPITCH;     // [32][256]

    const int part = blockIdx.x >> 6;     // 0: x->s1T, 1: y->s2
    const int cta  = blockIdx.x & 63;
    const float* W   = part ? W2 : W1;
    const float* src = part ? y  : x;

    const int tid = threadIdx.x;

    // Load + transpose W into Wsm[k][h].
    {
        const float4* W4 = (const float4*)W;
        const int h   = tid & 127;
        const int kq0 = tid >> 7;
        #pragma unroll
        for (int i = 0; i < 32; i++) {
            const int kq = kq0 + 2 * i;
            float4 wv = W4[h * 64 + kq];
            Wsm[(4 * kq + 0) * WPITCH + h] = wv.x;
            Wsm[(4 * kq + 1) * WPITCH + h] = wv.y;
            Wsm[(4 * kq + 2) * WPITCH + h] = wv.z;
            Wsm[(4 * kq + 3) * WPITCH + h] = wv.w;
        }
    }

    const int r0 = cta * 32;              // global row (b*512 + s/t)
    {
        const float4* s4 = (const float4*)(src + (size_t)r0 * DD);
        float4* d4 = (float4*)rowsm;
        #pragma unroll
        for (int i = 0; i < 8; i++)
            d4[tid + GA_THREADS * i] = s4[tid + GA_THREADS * i];
    }
    __syncthreads();

    const int w = tid >> 5, lane = tid & 31;
    float acc[4][4];                      // [row i][h component q]
    #pragma unroll
    for (int i = 0; i < 4; i++)
        #pragma unroll
        for (int q = 0; q < 4; q++) acc[i][q] = 0.0f;

    const float* rb = rowsm + (w * 4) * DD;

    #pragma unroll 4
    for (int k = 0; k < DD; k++) {
        float4 wv = *(const float4*)&Wsm[k * WPITCH + lane * 4];
        float xr0 = rb[k];
        float xr1 = rb[DD + k];
        float xr2 = rb[2 * DD + k];
        float xr3 = rb[3 * DD + k];
        acc[0][0] += xr0 * wv.x; acc[0][1] += xr0 * wv.y; acc[0][2] += xr0 * wv.z; acc[0][3] += xr0 * wv.w;
        acc[1][0] += xr1 * wv.x; acc[1][1] += xr1 * wv.y; acc[1][2] += xr1 * wv.z; acc[1][3] += xr1 * wv.w;
        acc[2][0] += xr2 * wv.x; acc[2][1] += xr2 * wv.y; acc[2][2] += xr2 * wv.z; acc[2][3] += xr2 * wv.w;
        acc[3][0] += xr3 * wv.x; acc[3][1] += xr3 * wv.y; acc[3][2] += xr3 * wv.z; acc[3][3] += xr3 * wv.w;
    }

    if (part == 0) {
        // transposed store: s1T[b][h][s], h = lane*4+q, s = (r0&511) + w*4 + i
        const int b  = r0 >> 9;
        const int sl = (r0 & 511) + w * 4;
        #pragma unroll
        for (int q = 0; q < 4; q++) {
            float4 tv = make_float4(acc[0][q], acc[1][q], acc[2][q], acc[3][q]);
            *(float4*)&g_s1[(size_t)b * (HH * SS) + (size_t)(lane * 4 + q) * SS + sl] = tv;
        }
    } else {
        #pragma unroll
        for (int i = 0; i < 4; i++) {
            float4 ov = make_float4(acc[i][0], acc[i][1], acc[i][2], acc[i][3]);
            *(float4*)&g_s2[(size_t)(r0 + w * 4 + i) * HH + lane * 4] = ov;
        }
    }
}

// ---------------------------------------------------------------------------
// Kernel B: fused score + softmax + weighted sum.
// TY=8 t-rows per CTA, grid = (64, 4) = 256 CTAs, 256 threads (8 warps).
// Pass 1: warp (hh = w>>2, sidx = w&3) computes partial scores for all 8 t,
//         s in [sidx*128, +128), h in [hh*64, +64). s1T read via contiguous
//         LDG.128 from L2; s2 packed [h][8t] broadcast from smem. 32 indep
//         accumulators per lane. No smem staging, no barriers in the loop.
// Pass 2: warp w = t index; x tiles staged in smem, all warps active.
// ---------------------------------------------------------------------------
#define TY 8
#define AT_THREADS 256

// smem layout (floats)
#define S2PK_OFF 0                         // [128][8]  = 1024
#define V_OFF    1024                      // [128]
#define RED_OFF  1152                      // [64]: [0..31] max grid, [32..63] sum grid
#define PSUM_OFF 1216                      // [8][512] = 4096 (partials -> weights)
#define BUF_OFF  5312                      // [32][256] = 8192 (pass-2 x tile)
#define SM_FLOATS 13504                    // 54016 bytes

__global__ __launch_bounds__(AT_THREADS, 2)
void attn_kernel(const float* __restrict__ x, const float* __restrict__ vc,
                 float* __restrict__ out)
{
    extern __shared__ float sm[];
    float* s2pk = sm + S2PK_OFF;
    float* vsm  = sm + V_OFF;
    float* red  = sm + RED_OFF;
    float* psum = sm + PSUM_OFF;
    float* buf  = sm + BUF_OFF;

    const int b   = blockIdx.y;
    const int t0  = blockIdx.x * TY;
    const int tid = threadIdx.x, w = tid >> 5, lane = tid & 31;
    const int sidx = w & 3;               // s quarter
    const int hh   = w >> 2;              // h half

    // Build s2pk[h][t] (t fast) and vsm.
    if (tid < 128) {
        const int h = tid;
        #pragma unroll
        for (int t = 0; t < TY; t++)
            s2pk[h * TY + t] = g_s2[(size_t)(b * SS + t0 + t) * HH + h];
    } else if (tid < 160) {
        const int l = tid - 128;
        *(float4*)&vsm[l * 4] = *(const float4*)&vc[l * 4];
    }
    __syncthreads();

    // ---- Pass 1: partial scores ---------------------------------------------
    const int sbase = sidx * 128 + lane * 4;     // lane's 4 s values
    const float* s1p = g_s1 + (size_t)b * (HH * SS) + (size_t)(hh * 64) * SS + sbase;
    const float* s2h = s2pk + (hh * 64) * TY;
    const float* vh  = vsm + hh * 64;

    float acc[32];                                // [t][c]
    #pragma unroll
    for (int i = 0; i < 32; i++) acc[i] = 0.0f;

    #pragma unroll 2
    for (int h = 0; h < 64; h++) {
        float4 av  = *(const float4*)(s1p + (size_t)h * SS);   // contiguous LDG.128
        float4 bt0 = *(const float4*)(s2h + h * TY);           // broadcast: t 0..3
        float4 bt1 = *(const float4*)(s2h + h * TY + 4);       // broadcast: t 4..7
        float  vv  = vh[h];                                    // broadcast
        float ax[4] = {av.x, av.y, av.z, av.w};
        float bx[8] = {bt0.x, bt0.y, bt0.z, bt0.w, bt1.x, bt1.y, bt1.z, bt1.w};
        #pragma unroll
        for (int t = 0; t < 8; t++)
            #pragma unroll
            for (int c = 0; c < 4; c++)
                acc[t * 4 + c] += tanh_fast(ax[c] + bx[t]) * vv;
    }

    // ---- Combine h-halves + softmax ------------------------------------------
    if (hh == 1) {
        #pragma unroll
        for (int t = 0; t < 8; t++)
            *(float4*)&psum[t * 512 + sbase] =
                make_float4(acc[t*4], acc[t*4+1], acc[t*4+2], acc[t*4+3]);
    }
    __syncthreads();

    float gm[8];
    if (hh == 0) {
        #pragma unroll
        for (int t = 0; t < 8; t++) {
            float4 p = *(const float4*)&psum[t * 512 + sbase];
            acc[t*4+0] += p.x; acc[t*4+1] += p.y; acc[t*4+2] += p.z; acc[t*4+3] += p.w;
            float m = fmaxf(fmaxf(acc[t*4], acc[t*4+1]), fmaxf(acc[t*4+2], acc[t*4+3]));
            #pragma unroll
            for (int o = 16; o > 0; o >>= 1) m = fmaxf(m, __shfl_xor_sync(0xffffffffu, m, o));
            gm[t] = m;
        }
        if (lane == 0) {
            #pragma unroll
            for (int t = 0; t < 8; t++) red[sidx * 8 + t] = gm[t];
        }
    }
    __syncthreads();

    if (hh == 0) {
        #pragma unroll
        for (int t = 0; t < 8; t++) {
            float M = fmaxf(fmaxf(red[t], red[8 + t]), fmaxf(red[16 + t], red[24 + t]));
            gm[t] = M;
            float s = 0.0f;
            #pragma unroll
            for (int c = 0; c < 4; c++) {
                float e = __expf(acc[t*4+c] - M);
                acc[t*4+c] = e; s += e;
            }
            #pragma unroll
            for (int o = 16; o > 0; o >>= 1) s += __shfl_xor_sync(0xffffffffu, s, o);
            if (lane == 0) red[32 + sidx * 8 + t] = s;
        }
    }
    __syncthreads();

    if (hh == 0) {
        #pragma unroll
        for (int t = 0; t < 8; t++) {
            float S = (red[32 + t] + red[40 + t]) + (red[48 + t] + red[56 + t]);
            float inv = 1.0f / S;
            *(float4*)&psum[t * 512 + sbase] =
                make_float4(acc[t*4] * inv, acc[t*4+1] * inv, acc[t*4+2] * inv, acc[t*4+3] * inv);
        }
    }
    // ordering of psum writes handled by the first barrier of the pass-2 loop

    // ---- Pass 2: out[t,:] = sum_s w[t][s] * x[b,s,:] -------------------------
    // warp w = t index; lane covers d = lane*4 (low half) and 128+lane*4.
    float4 acc0 = {0,0,0,0}, acc1 = {0,0,0,0};
    for (int sb = 0; sb < 16; sb++) {
        __syncthreads();
        const float4* xs = (const float4*)(x + (size_t)(b * SS + sb * 32) * DD);
        float4* bd = (float4*)buf;
        #pragma unroll
        for (int i = 0; i < 8; i++)
            bd[tid + AT_THREADS * i] = xs[tid + AT_THREADS * i];
        __syncthreads();

        const float* wr = psum + w * 512 + sb * 32;
        #pragma unroll
        for (int jq = 0; jq < 8; jq++) {
            float4 w4 = *(const float4*)&wr[jq * 4];     // broadcast
            float wtv[4] = {w4.x, w4.y, w4.z, w4.w};
            #pragma unroll
            for (int c = 0; c < 4; c++) {
                const int j = jq * 4 + c;
                const float wt = wtv[c];
                float4 xa = *(const float4*)&buf[j * DD + lane * 4];
                float4 xb = *(const float4*)&buf[j * DD + 128 + lane * 4];
                acc0.x += wt * xa.x; acc0.y += wt * xa.y;
                acc0.z += wt * xa.z; acc0.w += wt * xa.w;
                acc1.x += wt * xb.x; acc1.y += wt * xb.y;
                acc1.z += wt * xb.z; acc1.w += wt * xb.w;
            }
        }
    }

    float* o = out + (size_t)(b * SS + t0 + w) * DD;
    *(float4*)&o[lane * 4]       = acc0;
    *(float4*)&o[128 + lane * 4] = acc1;
}

// ---------------------------------------------------------------------------
extern "C" void kernel_launch(void* const* d_in, const int* in_sizes, int n_in,
                              void* d_out, int out_size)
{
    const float* x   = (const float*)d_in[0];   // (4,512,256)
    const float* y   = (const float*)d_in[1];   // (4,512,256)
    const float* W1  = (const float*)d_in[2];   // (128,256)
    const float* W2  = (const float*)d_in[3];   // (128,256)
    const float* vc  = (const float*)d_in[4];   // (1,128)
    float* out = (float*)d_out;                 // (4,512,256)

    const size_t smA = (size_t)(256 * WPITCH + 32 * 256) * sizeof(float);
    const size_t smB = (size_t)SM_FLOATS * sizeof(float);   // 54016 B

    cudaFuncSetAttribute(proj_kernel, cudaFuncAttributeMaxDynamicSharedMemorySize, (int)smA);
    cudaFuncSetAttribute(attn_kernel, cudaFuncAttributeMaxDynamicSharedMemorySize, (int)smB);

    proj_kernel<<<128, GA_THREADS, smA>>>(x, y, W1, W2);
    attn_kernel<<<dim3(SS / TY, BB), AT_THREADS, smB>>>(x, vc, out);
}